// round 8
// baseline (speedup 1.0000x reference)
#include <cuda_runtime.h>

// WeightedLoss: mean over 64M elems of (target==1 ? 1-sigmoid(pred) : 0.1)
// 1 - sigmoid(x) = 0.5 - 0.5*tanh(x/2)  -> single MUFU.TANH per element
//
// R6: R1's proven stream config (grid=2048, simple loop, plain LDG.E.128)
//     + fused last-block final reduce (saves 4.4us second launch).
// Deterministic: fixed partial order, fixed final-sum order.

#define NBLOCKS 2048
#define NTHREADS 256

__device__ float g_partials[NBLOCKS];
__device__ unsigned int g_arrive = 0;   // re-armed to 0 by the last block each run

__device__ __forceinline__ float elem_loss(float p, int t) {
    float s = 0.5f - 0.5f * __tanhf(0.5f * p);   // = 1 - sigmoid(p)
    return (t == 1) ? s : 0.1f;
}

__global__ __launch_bounds__(NTHREADS)
void wl_fused_kernel(const float* __restrict__ pred,
                     const int* __restrict__ tgt,
                     int n, float inv_n,
                     float* __restrict__ out)
{
    const float4* __restrict__ p4 = reinterpret_cast<const float4*>(pred);
    const int4*   __restrict__ t4 = reinterpret_cast<const int4*>(tgt);
    const int n4 = n >> 2;   // 64M divisible by 4

    float acc = 0.0f;
    const int stride = gridDim.x * blockDim.x;
    for (int i = blockIdx.x * blockDim.x + threadIdx.x; i < n4; i += stride) {
        float4 p = p4[i];   // plain LDG.E.128 (R2: .cs hurts; R5: manual unroll neutral)
        int4   t = t4[i];
        acc += elem_loss(p.x, t.x) + elem_loss(p.y, t.y)
             + elem_loss(p.z, t.z) + elem_loss(p.w, t.w);
    }

    // intra-block reduce
    #pragma unroll
    for (int o = 16; o > 0; o >>= 1)
        acc += __shfl_xor_sync(0xffffffffu, acc, o);

    __shared__ float sw[NTHREADS / 32];
    __shared__ bool s_last;
    if ((threadIdx.x & 31) == 0) sw[threadIdx.x >> 5] = acc;
    __syncthreads();

    if (threadIdx.x < 32) {
        float v = (threadIdx.x < NTHREADS / 32) ? sw[threadIdx.x] : 0.0f;
        #pragma unroll
        for (int o = 4; o > 0; o >>= 1)
            v += __shfl_xor_sync(0xffffffffu, v, o);
        if (threadIdx.x == 0) {
            g_partials[blockIdx.x] = v;
            __threadfence();
            unsigned int prev = atomicAdd(&g_arrive, 1u);
            s_last = (prev == (unsigned int)(gridDim.x - 1));
        }
    }
    __syncthreads();

    // last block performs the final reduction (fixed order: deterministic)
    if (s_last) {
        float a = 0.0f;
        for (int j = threadIdx.x; j < NBLOCKS; j += NTHREADS)
            a += g_partials[j];   // 8 per thread, fixed order

        #pragma unroll
        for (int o = 16; o > 0; o >>= 1)
            a += __shfl_xor_sync(0xffffffffu, a, o);

        __shared__ float sw2[NTHREADS / 32];
        if ((threadIdx.x & 31) == 0) sw2[threadIdx.x >> 5] = a;
        __syncthreads();

        if (threadIdx.x < 32) {
            float v = (threadIdx.x < NTHREADS / 32) ? sw2[threadIdx.x] : 0.0f;
            #pragma unroll
            for (int o = 4; o > 0; o >>= 1)
                v += __shfl_xor_sync(0xffffffffu, v, o);
            if (threadIdx.x == 0) {
                out[0] = v * inv_n;
                __threadfence();
                g_arrive = 0;   // re-arm for next graph replay
            }
        }
    }
}

extern "C" void kernel_launch(void* const* d_in, const int* in_sizes, int n_in,
                              void* d_out, int out_size)
{
    const float* pred = (const float*)d_in[0];
    const int*   tgt  = (const int*)d_in[1];
    float*       out  = (float*)d_out;
    const int n = in_sizes[0];

    wl_fused_kernel<<<NBLOCKS, NTHREADS>>>(pred, tgt, n, 1.0f / (float)n, out);
}

// round 10
// speedup vs baseline: 1.0213x; 1.0213x over previous
#include <cuda_runtime.h>

// WeightedLoss: mean over 64M elems of (target==1 ? 1-sigmoid(pred) : 0.1)
// 1 - sigmoid(x) = 0.5 - 0.5*tanh(x/2)  -> single MUFU.TANH per element
//
// Best-known config (R3): grid=1184 fully-resident, 256 thr, simple loop,
// fused last-block reduce. R9 change: __ldcg (L2-only) loads — zero-reuse
// stream, skip L1 fill. (.cs hurt in R2: evict-first policy, different knob.)

#define NBLOCKS (148 * 8)
#define NTHREADS 256

__device__ float g_partials[NBLOCKS];
__device__ unsigned int g_arrive = 0;   // re-armed to 0 by the last block each run

__device__ __forceinline__ float elem_loss(float p, int t) {
    float s = 0.5f - 0.5f * __tanhf(0.5f * p);   // = 1 - sigmoid(p)
    return (t == 1) ? s : 0.1f;
}

__global__ __launch_bounds__(NTHREADS)
void wl_fused_kernel(const float* __restrict__ pred,
                     const int* __restrict__ tgt,
                     int n, float inv_n,
                     float* __restrict__ out)
{
    const float4* __restrict__ p4 = reinterpret_cast<const float4*>(pred);
    const int4*   __restrict__ t4 = reinterpret_cast<const int4*>(tgt);
    const int n4 = n >> 2;   // 64M divisible by 4

    float acc = 0.0f;
    const int stride = gridDim.x * blockDim.x;
    for (int i = blockIdx.x * blockDim.x + threadIdx.x; i < n4; i += stride) {
        float4 p = __ldcg(&p4[i]);   // LDG.E.128.CG — L2-only, evict-normal
        int4   t = __ldcg(&t4[i]);
        acc += elem_loss(p.x, t.x) + elem_loss(p.y, t.y)
             + elem_loss(p.z, t.z) + elem_loss(p.w, t.w);
    }

    // intra-block reduce
    #pragma unroll
    for (int o = 16; o > 0; o >>= 1)
        acc += __shfl_xor_sync(0xffffffffu, acc, o);

    __shared__ float sw[NTHREADS / 32];
    __shared__ bool s_last;
    if ((threadIdx.x & 31) == 0) sw[threadIdx.x >> 5] = acc;
    __syncthreads();

    if (threadIdx.x < 32) {
        float v = (threadIdx.x < NTHREADS / 32) ? sw[threadIdx.x] : 0.0f;
        #pragma unroll
        for (int o = 4; o > 0; o >>= 1)
            v += __shfl_xor_sync(0xffffffffu, v, o);
        if (threadIdx.x == 0) {
            g_partials[blockIdx.x] = v;
            __threadfence();
            unsigned int prev = atomicAdd(&g_arrive, 1u);
            s_last = (prev == (unsigned int)(gridDim.x - 1));
        }
    }
    __syncthreads();

    // last block performs the final reduction (fixed order: deterministic)
    if (s_last) {
        float a = 0.0f;
        for (int j = threadIdx.x; j < NBLOCKS; j += NTHREADS)
            a += g_partials[j];   // fixed order

        #pragma unroll
        for (int o = 16; o > 0; o >>= 1)
            a += __shfl_xor_sync(0xffffffffu, a, o);

        __shared__ float sw2[NTHREADS / 32];
        if ((threadIdx.x & 31) == 0) sw2[threadIdx.x >> 5] = a;
        __syncthreads();

        if (threadIdx.x < 32) {
            float v = (threadIdx.x < NTHREADS / 32) ? sw2[threadIdx.x] : 0.0f;
            #pragma unroll
            for (int o = 4; o > 0; o >>= 1)
                v += __shfl_xor_sync(0xffffffffu, v, o);
            if (threadIdx.x == 0) {
                out[0] = v * inv_n;
                __threadfence();
                g_arrive = 0;   // re-arm for next graph replay
            }
        }
    }
}

extern "C" void kernel_launch(void* const* d_in, const int* in_sizes, int n_in,
                              void* d_out, int out_size)
{
    const float* pred = (const float*)d_in[0];
    const int*   tgt  = (const int*)d_in[1];
    float*       out  = (float*)d_out;
    const int n = in_sizes[0];

    wl_fused_kernel<<<NBLOCKS, NTHREADS>>>(pred, tgt, n, 1.0f / (float)n, out);
}

// round 14
// speedup vs baseline: 1.0292x; 1.0078x over previous
#include <cuda_runtime.h>

// WeightedLoss: mean over 64M elems of (target==1 ? 1-sigmoid(pred) : 0.1)
// 1 - sigmoid(x) = 0.5 - 0.5*tanh(x/2)  -> single MUFU.TANH per element
//
// R11: Blackwell 256-bit vector loads (ld.global.v8 -> LDG.E.256):
// half the load instructions / L1tex queue entries for the same bytes.
// Best-known config otherwise: grid=1184, 256 thr, default cache policy,
// fused last-block reduce (deterministic, fixed order).

#define NBLOCKS (148 * 8)
#define NTHREADS 256

__device__ float g_partials[NBLOCKS];
__device__ unsigned int g_arrive = 0;   // re-armed to 0 by the last block each run

__device__ __forceinline__ float elem_loss(float p, int t) {
    float s = 0.5f - 0.5f * __tanhf(0.5f * p);   // = 1 - sigmoid(p)
    return (t == 1) ? s : 0.1f;
}

__device__ __forceinline__ void ldg256_f32(const float* a, float* v) {
    asm volatile("ld.global.v8.f32 {%0,%1,%2,%3,%4,%5,%6,%7}, [%8];"
                 : "=f"(v[0]), "=f"(v[1]), "=f"(v[2]), "=f"(v[3]),
                   "=f"(v[4]), "=f"(v[5]), "=f"(v[6]), "=f"(v[7])
                 : "l"(a));
}

__device__ __forceinline__ void ldg256_s32(const int* a, int* v) {
    asm volatile("ld.global.v8.u32 {%0,%1,%2,%3,%4,%5,%6,%7}, [%8];"
                 : "=r"(v[0]), "=r"(v[1]), "=r"(v[2]), "=r"(v[3]),
                   "=r"(v[4]), "=r"(v[5]), "=r"(v[6]), "=r"(v[7])
                 : "l"(a));
}

__global__ __launch_bounds__(NTHREADS)
void wl_fused_kernel(const float* __restrict__ pred,
                     const int* __restrict__ tgt,
                     int n, float inv_n,
                     float* __restrict__ out)
{
    const int n8 = n >> 3;   // 64M divisible by 8; 32B-aligned accesses

    float acc = 0.0f;
    const int stride = gridDim.x * blockDim.x;
    for (int i = blockIdx.x * blockDim.x + threadIdx.x; i < n8; i += stride) {
        float p[8];
        int   t[8];
        ldg256_f32(pred + (size_t)i * 8, p);   // LDG.E.256
        ldg256_s32(tgt  + (size_t)i * 8, t);   // LDG.E.256
        #pragma unroll
        for (int k = 0; k < 8; k++)
            acc += elem_loss(p[k], t[k]);
    }

    // intra-block reduce
    #pragma unroll
    for (int o = 16; o > 0; o >>= 1)
        acc += __shfl_xor_sync(0xffffffffu, acc, o);

    __shared__ float sw[NTHREADS / 32];
    __shared__ bool s_last;
    if ((threadIdx.x & 31) == 0) sw[threadIdx.x >> 5] = acc;
    __syncthreads();

    if (threadIdx.x < 32) {
        float v = (threadIdx.x < NTHREADS / 32) ? sw[threadIdx.x] : 0.0f;
        #pragma unroll
        for (int o = 4; o > 0; o >>= 1)
            v += __shfl_xor_sync(0xffffffffu, v, o);
        if (threadIdx.x == 0) {
            g_partials[blockIdx.x] = v;
            __threadfence();
            unsigned int prev = atomicAdd(&g_arrive, 1u);
            s_last = (prev == (unsigned int)(gridDim.x - 1));
        }
    }
    __syncthreads();

    // last block performs the final reduction (fixed order: deterministic)
    if (s_last) {
        float a = 0.0f;
        for (int j = threadIdx.x; j < NBLOCKS; j += NTHREADS)
            a += g_partials[j];   // fixed order

        #pragma unroll
        for (int o = 16; o > 0; o >>= 1)
            a += __shfl_xor_sync(0xffffffffu, a, o);

        __shared__ float sw2[NTHREADS / 32];
        if ((threadIdx.x & 31) == 0) sw2[threadIdx.x >> 5] = a;
        __syncthreads();

        if (threadIdx.x < 32) {
            float v = (threadIdx.x < NTHREADS / 32) ? sw2[threadIdx.x] : 0.0f;
            #pragma unroll
            for (int o = 4; o > 0; o >>= 1)
                v += __shfl_xor_sync(0xffffffffu, v, o);
            if (threadIdx.x == 0) {
                out[0] = v * inv_n;
                __threadfence();
                g_arrive = 0;   // re-arm for next graph replay
            }
        }
    }
}

extern "C" void kernel_launch(void* const* d_in, const int* in_sizes, int n_in,
                              void* d_out, int out_size)
{
    const float* pred = (const float*)d_in[0];
    const int*   tgt  = (const int*)d_in[1];
    float*       out  = (float*)d_out;
    const int n = in_sizes[0];

    wl_fused_kernel<<<NBLOCKS, NTHREADS>>>(pred, tgt, n, 1.0f / (float)n, out);
}